// round 5
// baseline (speedup 1.0000x reference)
#include <cuda_runtime.h>
#include <cuda_fp16.h>
#include <cstdint>

#define BB   16
#define HH   512
#define WW   512
#define HW   (HH * WW)
#define NPIX (BB * HW)

typedef unsigned int u32;

// Symmetric factorization: A_d(p) = A_{-d}(p+d) for the unnormalized entries,
// center entry is the constant exp(1). 4 forward-direction planes of
// A = exp(e) (fp16) + one plane of invS' = 0.5*weight/S (fp16).
// Dirs: 0=(0,1) 1=(1,-1) 2=(1,0) 3=(1,1)
__device__ __half g_A[4][NPIX];    // 33.6 MB
__device__ __half g_invS[NPIX];    //  8.4 MB
__device__ float  g_buf[2][NPIX];  // ping-pong pred buffers

#define AC 2.7182818284590452f     // exp(1): center softmax-numerator

__global__ __launch_bounds__(256)
void build_kernel(const float* __restrict__ image,
                  const float* __restrict__ theta,
                  const float* __restrict__ weight)
{
    int idx = blockIdx.x * 256 + threadIdx.x;
    if (idx >= NPIX) return;
    int w = idx & (WW - 1);
    int h = (idx >> 9) & (HH - 1);
    int b = idx >> 18;

    float t0 = theta[0], t1 = theta[1], t2 = theta[2];
    const float* img = image + b * HW;
    float c = img[h * WW + w] * 255.0f;

    float A[9];
#pragma unroll
    for (int k = 0; k < 9; k++) {
        int dx = k / 3 - 1, dy = k % 3 - 1;
        int hh = h + dx, ww = w + dy;
        float e = 0.0f;
        if ((unsigned)hh < HH && (unsigned)ww < WW) {
            float d    = img[hh * WW + ww] * 255.0f - c;
            float dist = t0 * (float)(dx * dx) + t1 * (float)(dy * dy) + t2 * d * d;
            e = __expf(-0.5f * dist);
        }
        A[k] = __expf(e);          // invalid neighbor -> exp(0) = 1
    }

    // Sum S from the fp16-ROUNDED values: exactly what the message pass reads.
    float S = AC;
#pragma unroll
    for (int k = 0; k < 9; k++)
        if (k != 4) S += __half2float(__float2half(A[k]));

    float invSw = 0.5f * weight[0] / S;
    g_A[0][idx] = __float2half(A[5]);   // (0, 1)
    g_A[1][idx] = __float2half(A[6]);   // (1,-1)
    g_A[2][idx] = __float2half(A[7]);   // (1, 0)
    g_A[3][idx] = __float2half(A[8]);   // (1, 1)
    g_invS[idx] = __float2half(invSw);
}

// ---------------------------------------------------------------------------
// Message core: 9 unconditional FMA terms. OOB-of-image smem slots hold
// pred=0 (so A value there is irrelevant) and A=1 (finite), giving exact
// reference boundary semantics without branches.
// PS = pred smem stride, AS = A smem stride.
// ---------------------------------------------------------------------------
__device__ __forceinline__ float msg_core(
    const float* pc, int PS,
    const __half* a0, const __half* a1, const __half* a2, const __half* a3,
    int AS, float isv, float uv)
{
    float a = AC * pc[0];
    a += __half2float(a0[0])       * pc[1];        // dir0 fwd (0,+1)
    a += __half2float(a0[-1])      * pc[-1];       // dir0 bwd (0,-1)
    a += __half2float(a1[0])       * pc[PS - 1];   // dir1 fwd (+1,-1)
    a += __half2float(a1[-AS + 1]) * pc[-PS + 1];  // dir1 bwd (-1,+1)
    a += __half2float(a2[0])       * pc[PS];       // dir2 fwd (+1,0)
    a += __half2float(a2[-AS])     * pc[-PS];      // dir2 bwd (-1,0)
    a += __half2float(a3[0])       * pc[PS + 1];   // dir3 fwd (+1,+1)
    a += __half2float(a3[-AS - 1]) * pc[-PS - 1];  // dir3 bwd (-1,-1)
    return 0.5f * uv + isv * a;
}

// ---------------------------------------------------------------------------
// Fused double message pass: one launch = 2 Jacobi iterations per 16x128 tile.
// Frames (global coords):
//   s_in : rows [r0-2, r0+18), cols [c0-2, c0+130)   20 x 132 fp32
//   s_A  : rows [r0-2, r0+17), cols [c0-2, c0+130)   19 x 132 fp16 x4
//   s_is : rows [r0-1, r0+17), cols [c0-1, c0+129)   18 x 130 fp16
//   s_mid: rows [r0-1, r0+17), cols [c0-1, c0+129)   18 x 130 fp32
// ---------------------------------------------------------------------------
__global__ __launch_bounds__(256)
void fused2_pass(const float* __restrict__ pin,
                 const float* __restrict__ unary,
                 float* __restrict__ pout)
{
    __shared__ float  s_in[20][132];
    __shared__ float  s_mid[18][130];
    __shared__ __half s_A[4][19][132];
    __shared__ __half s_is[18][130];

    int t   = threadIdx.x;
    int blk = blockIdx.x;
    int b   = blk >> 7;             // 128 tiles per image (32 x 4)
    int tr  = (blk >> 2) & 31;
    int tc  = blk & 3;
    int r0  = tr * 16, c0 = tc * 128;
    int base = b * HW;

    const __half ONEH = __float2half(1.0f);

    // stage pred_in (halo 2), zero at global OOB
    for (int e = t; e < 20 * 132; e += 256) {
        int rr = e / 132, cc = e - rr * 132;
        int gh = r0 - 2 + rr, gw = c0 - 2 + cc;
        float v = 0.0f;
        if ((unsigned)gh < HH && (unsigned)gw < WW)
            v = pin[base + gh * WW + gw];
        s_in[rr][cc] = v;
    }
    // stage A planes (halo 2) + invS (halo 1), neutral values at global OOB
    for (int e = t; e < 19 * 132; e += 256) {
        int rr = e / 132, cc = e - rr * 132;
        int gh = r0 - 2 + rr, gw = c0 - 2 + cc;
        bool ok = (unsigned)gh < HH && (unsigned)gw < WW;
        int i = base + gh * WW + gw;
        s_A[0][rr][cc] = ok ? g_A[0][i] : ONEH;
        s_A[1][rr][cc] = ok ? g_A[1][i] : ONEH;
        s_A[2][rr][cc] = ok ? g_A[2][i] : ONEH;
        s_A[3][rr][cc] = ok ? g_A[3][i] : ONEH;
        if (rr >= 1 && cc >= 1 && cc <= 130)
            s_is[rr - 1][cc - 1] = ok ? g_invS[i] : ONEH;
    }
    __syncthreads();

    // phase 1: iteration i+1 on halo-1 region (18 x 130)
    for (int e = t; e < 18 * 130; e += 256) {
        int mr = e / 130, mc = e - mr * 130;
        int gh = r0 - 1 + mr, gw = c0 - 1 + mc;
        float v = 0.0f;
        if ((unsigned)gh < HH && (unsigned)gw < WW) {
            v = msg_core(&s_in[mr + 1][mc + 1], 132,
                         &s_A[0][mr + 1][mc + 1], &s_A[1][mr + 1][mc + 1],
                         &s_A[2][mr + 1][mc + 1], &s_A[3][mr + 1][mc + 1], 132,
                         __half2float(s_is[mr][mc]),
                         unary[base + gh * WW + gw]);
        }
        s_mid[mr][mc] = v;
    }
    __syncthreads();

    // phase 2: iteration i+2 on the tile (16 x 128), write global
    for (int e = t; e < 16 * 128; e += 256) {
        int mr = e >> 7, mc = e & 127;
        int gh = r0 + mr, gw = c0 + mc;
        int i  = base + gh * WW + gw;
        float v = msg_core(&s_mid[mr + 1][mc + 1], 130,
                           &s_A[0][mr + 2][mc + 2], &s_A[1][mr + 2][mc + 2],
                           &s_A[2][mr + 2][mc + 2], &s_A[3][mr + 2][mc + 2], 132,
                           __half2float(s_is[mr + 1][mc + 1]),
                           unary[i]);
        pout[i] = v;
    }
}

extern "C" void kernel_launch(void* const* d_in, const int* in_sizes, int n_in,
                              void* d_out, int out_size)
{
    const float* image  = (const float*)d_in[0];
    const float* unary  = (const float*)d_in[1];
    const float* theta  = (const float*)d_in[2];
    const float* weight = (const float*)d_in[3];
    float* out = (float*)d_out;

    void* baddr = nullptr;
    cudaGetSymbolAddress(&baddr, g_buf);   // non-stream API: capture-safe
    float* buf0 = (float*)baddr;
    float* buf1 = buf0 + NPIX;

    build_kernel<<<NPIX / 256, 256>>>(image, theta, weight);

    // 5 fused launches = 10 iterations
    for (int l = 0; l < 5; l++) {
        const float* pin  = (l == 0) ? unary : ((l & 1) ? buf0 : buf1);
        float*       pout = (l == 4) ? out   : ((l & 1) ? buf1 : buf0);
        fused2_pass<<<BB * 128, 256>>>(pin, unary, pout);
    }
}

// round 6
// speedup vs baseline: 1.4412x; 1.4412x over previous
#include <cuda_runtime.h>
#include <cuda_fp16.h>
#include <cstdint>

#define BB   16
#define HH   512
#define WW   512
#define HW   (HH * WW)
#define NPIX (BB * HW)

#define PADP  520                       // per-image pad (front & back), >= WW+8
#define IMSTR (HW + 2 * PADP)           // padded image stride
#define TOT   (BB * IMSTR)

typedef unsigned int u32;

// Interleaved forward weights: g_AI[pixel*4 + d] = A_d(pixel), fp16, padded
// per image so all row-shifted reads are in-bounds (pads are zeroed: finite,
// always multiplied by pred=0). Dirs: 0=(0,1) 1=(1,-1) 2=(1,0) 3=(1,1)
__device__ __half g_AI[(size_t)TOT * 4];   // 33.7 MB
__device__ __half g_invS[TOT];             //  8.4 MB (pads never touched)
__device__ float  g_buf[2][TOT];           // padded ping-pong pred buffers

#define AC 2.7182818284590452f     // exp(1): center softmax-numerator

// ---------------------------------------------------------------------------
// Zero the pad strips of pred buffers and A array (16 images x 1040 pad px).
// ---------------------------------------------------------------------------
__global__ __launch_bounds__(256)
void init_pads()
{
    int e = blockIdx.x * 256 + threadIdx.x;
    if (e >= BB * 2 * PADP) return;
    int b = e / (2 * PADP);
    int j = e - b * (2 * PADP);
    int off = (j < PADP) ? (b * IMSTR + j)
                         : (b * IMSTR + PADP + HW + (j - PADP));
    g_buf[0][off] = 0.0f;
    g_buf[1][off] = 0.0f;
    *(uint2*)&g_AI[(size_t)off * 4] = make_uint2(0u, 0u);
}

__global__ __launch_bounds__(256)
void build_kernel(const float* __restrict__ image,
                  const float* __restrict__ theta,
                  const float* __restrict__ weight)
{
    int idx = blockIdx.x * 256 + threadIdx.x;
    if (idx >= NPIX) return;
    int w = idx & (WW - 1);
    int h = (idx >> 9) & (HH - 1);
    int b = idx >> 18;

    float t0 = theta[0], t1 = theta[1], t2 = theta[2];
    const float* img = image + b * HW;
    float c = img[h * WW + w] * 255.0f;

    float A[9];
#pragma unroll
    for (int k = 0; k < 9; k++) {
        int dx = k / 3 - 1, dy = k % 3 - 1;
        int hh = h + dx, ww = w + dy;
        float e = 0.0f;
        if ((unsigned)hh < HH && (unsigned)ww < WW) {
            float d    = img[hh * WW + ww] * 255.0f - c;
            float dist = t0 * (float)(dx * dx) + t1 * (float)(dy * dy) + t2 * d * d;
            e = __expf(-0.5f * dist);
        }
        A[k] = __expf(e);          // invalid neighbor -> exp(0) = 1
    }

    // Sum S from the fp16-ROUNDED values: exactly what the message pass reads
    // (forward at p and backward at p-d are bit-identical by symmetry).
    float S = AC;
#pragma unroll
    for (int k = 0; k < 9; k++)
        if (k != 4) S += __half2float(__float2half(A[k]));

    int pidx = b * IMSTR + PADP + h * WW + w;
    __half2 lo = __halves2half2(__float2half(A[5]), __float2half(A[6]));
    __half2 hi = __halves2half2(__float2half(A[7]), __float2half(A[8]));
    *(uint2*)&g_AI[(size_t)pidx * 4] =
        make_uint2(*(u32*)&lo, *(u32*)&hi);
    g_invS[pidx] = __float2half(0.5f * weight[0] / S);
}

__device__ __forceinline__ float2 h2f(const u32 u) {
    return __half22float2(*reinterpret_cast<const __half2*>(&u));
}

// ---------------------------------------------------------------------------
// One Jacobi iteration, quad (4 px) per thread.
// FIRST: pred-in = unary (unpadded, needs row checks).
// else : pred-in = padded buffer (row reads unconditional; pads are zero).
// ---------------------------------------------------------------------------
template<bool FIRST>
__global__ __launch_bounds__(256)
void message_pass(const float* __restrict__ pin,
                  const float* __restrict__ unary,
                  float* __restrict__ pout, int out_padded)
{
    int q = blockIdx.x * 256 + threadIdx.x;
    if (q >= NPIX / 4) return;
    int w4 = (q & (WW / 4 - 1)) << 2;
    int h  = (q >> 7) & (HH - 1);
    int b  = q >> 16;
    int uidx = b * HW    + h * WW + w4;          // unpadded index
    int pidx = b * IMSTR + PADP + h * WW + w4;   // padded index

    // pred neighborhood: 3 rows x cols [w4-1 .. w4+4]
    float row[3][6];
#pragma unroll
    for (int r = 0; r < 3; r++) {
        if (FIRST) {
            int gh = h + r - 1;
            if ((unsigned)gh >= HH) {
#pragma unroll
                for (int c = 0; c < 6; c++) row[r][c] = 0.0f;
                continue;
            }
            const float* p = pin + uidx + (r - 1) * WW;
            float4 v = *(const float4*)p;
            row[r][1] = v.x; row[r][2] = v.y; row[r][3] = v.z; row[r][4] = v.w;
            row[r][0] = (w4 > 0)      ? p[-1] : 0.0f;
            row[r][5] = (w4 + 4 < WW) ? p[4]  : 0.0f;
        } else {
            const float* p = pin + pidx + (r - 1) * WW;  // pads give zeros
            float4 v = *(const float4*)p;
            row[r][1] = v.x; row[r][2] = v.y; row[r][3] = v.z; row[r][4] = v.w;
            row[r][0] = (w4 > 0)      ? p[-1] : 0.0f;
            row[r][5] = (w4 + 4 < WW) ? p[4]  : 0.0f;
        }
    }

    // ---- A loads: all unconditional (padding guarantees in-bounds, finite)
    const __half* AI = g_AI;
    uint4 f01 = *(const uint4*)&AI[(size_t)pidx * 4];        // px p,p+1
    uint4 f23 = *(const uint4*)&AI[(size_t)pidx * 4 + 8];    // px p+2,p+3
    uint2 bm  = *(const uint2*)&AI[(size_t)(pidx - 1) * 4];  // px p-1
    int u = pidx - WW;
    uint2 um1 = *(const uint2*)&AI[(size_t)(u - 1) * 4];     // px u-1
    uint4 u01 = *(const uint4*)&AI[(size_t)u * 4];           // px u,u+1
    uint4 u23 = *(const uint4*)&AI[(size_t)u * 4 + 8];       // px u+2,u+3
    uint2 up4 = *(const uint2*)&AI[(size_t)(u + 4) * 4];     // px u+4

    float2 p0lo = h2f(f01.x), p0hi = h2f(f01.y);   // (d0,d1),(d2,d3)
    float2 p1lo = h2f(f01.z), p1hi = h2f(f01.w);
    float2 p2lo = h2f(f23.x), p2hi = h2f(f23.y);
    float2 p3lo = h2f(f23.z), p3hi = h2f(f23.w);
    float2 bmlo = h2f(bm.x);
    float2 m1hi = h2f(um1.y);
    float2 u0lo = h2f(u01.x), u0hi = h2f(u01.y);
    float2 u1lo = h2f(u01.z), u1hi = h2f(u01.w);
    float2 u2lo = h2f(u23.x), u2hi = h2f(u23.y);
    float2 u3lo = h2f(u23.z), u3hi = h2f(u23.w);
    float2 u4lo = h2f(up4.x);

    // a_j = AC*ctr + fwd(d0..d3) + bwd(d0..d3)
    float a0 = AC * row[1][1]
             + p0lo.x * row[1][2] + p0lo.y * row[2][0]
             + p0hi.x * row[2][1] + p0hi.y * row[2][2]
             + bmlo.x * row[1][0] + u1lo.y * row[0][2]
             + u0hi.x * row[0][1] + m1hi.y * row[0][0];
    float a1 = AC * row[1][2]
             + p1lo.x * row[1][3] + p1lo.y * row[2][1]
             + p1hi.x * row[2][2] + p1hi.y * row[2][3]
             + p0lo.x * row[1][1] + u2lo.y * row[0][3]
             + u1hi.x * row[0][2] + u0hi.y * row[0][1];
    float a2 = AC * row[1][3]
             + p2lo.x * row[1][4] + p2lo.y * row[2][2]
             + p2hi.x * row[2][3] + p2hi.y * row[2][4]
             + p1lo.x * row[1][2] + u3lo.y * row[0][4]
             + u2hi.x * row[0][3] + u1hi.y * row[0][2];
    float a3 = AC * row[1][4]
             + p3lo.x * row[1][5] + p3lo.y * row[2][3]
             + p3hi.x * row[2][4] + p3hi.y * row[2][5]
             + p2lo.x * row[1][3] + u4lo.y * row[0][5]
             + u3hi.x * row[0][4] + u2hi.y * row[0][3];

    uint2 sv = *(const uint2*)&g_invS[pidx];
    float2 s01 = h2f(sv.x), s23 = h2f(sv.y);
    float4 uv = *(const float4*)(unary + uidx);
    float4 o;
    o.x = 0.5f * uv.x + s01.x * a0;
    o.y = 0.5f * uv.y + s01.y * a1;
    o.z = 0.5f * uv.z + s23.x * a2;
    o.w = 0.5f * uv.w + s23.y * a3;
    if (out_padded) *(float4*)(pout + pidx) = o;
    else            *(float4*)(pout + uidx) = o;
}

extern "C" void kernel_launch(void* const* d_in, const int* in_sizes, int n_in,
                              void* d_out, int out_size)
{
    const float* image  = (const float*)d_in[0];
    const float* unary  = (const float*)d_in[1];
    const float* theta  = (const float*)d_in[2];
    const float* weight = (const float*)d_in[3];
    float* out = (float*)d_out;

    void* baddr = nullptr;
    cudaGetSymbolAddress(&baddr, g_buf);   // non-stream API: capture-safe
    float* buf0 = (float*)baddr;
    float* buf1 = buf0 + TOT;

    init_pads<<<(BB * 2 * PADP + 255) / 256, 256>>>();
    build_kernel<<<NPIX / 256, 256>>>(image, theta, weight);

    for (int i = 0; i < 10; i++) {
        float* pout = (i == 9) ? out : ((i & 1) ? buf1 : buf0);
        int    padded = (i != 9);
        if (i == 0)
            message_pass<true><<<4096, 256>>>(unary, unary, pout, padded);
        else
            message_pass<false><<<4096, 256>>>(((i - 1) & 1) ? buf1 : buf0,
                                               unary, pout, padded);
    }
}

// round 8
// speedup vs baseline: 1.7403x; 1.2075x over previous
#include <cuda_runtime.h>
#include <cuda_fp16.h>
#include <cstdint>

#define BB   16
#define HH   512
#define WW   512
#define HW   (HH * WW)
#define NPIX (BB * HW)

typedef unsigned int u32;
typedef unsigned long long u64;

// Symmetric factorization: A_d(p) = A_{-d}(p+d) for the unnormalized entries,
// center entry is the constant exp(1). 4 forward-direction planes of
// A = exp(e) (fp16) + one plane of invS' = 0.5*weight/S (fp16).
// Dirs: 0=(0,1) 1=(1,-1) 2=(1,0) 3=(1,1)
__device__ __half g_A[4][NPIX];    // 33.6 MB  (evict_last: 10x reused)
__device__ __half g_invS[NPIX];    //  8.4 MB  (evict_last)
__device__ float  g_buf[2][NPIX];  // ping-pong pred buffers (default policy)

#define AC 2.7182818284590452f     // exp(1): center softmax-numerator

// ---- L2 retention-priority loads via createpolicy + cache_hint -------------
__device__ __forceinline__ u64 mk_policy() {
    u64 pol;
    asm("createpolicy.fractional.L2::evict_last.b64 %0, 1.0;" : "=l"(pol));
    return pol;
}
__device__ __forceinline__ u32 ldg_el_u1(const void* p, u64 pol) {
    u32 v;
    asm("ld.global.nc.L2::cache_hint.u32 %0, [%1], %2;"
        : "=r"(v) : "l"(p), "l"(pol));
    return v;
}
__device__ __forceinline__ uint2 ldg_el_u2(const void* p, u64 pol) {
    uint2 v;
    asm("ld.global.nc.L2::cache_hint.v2.u32 {%0,%1}, [%2], %3;"
        : "=r"(v.x), "=r"(v.y) : "l"(p), "l"(pol));
    return v;
}
__device__ __forceinline__ float4 ldg_el_f4(const void* p, u64 pol) {
    float4 v;
    asm("ld.global.nc.L2::cache_hint.v4.f32 {%0,%1,%2,%3}, [%4], %5;"
        : "=f"(v.x), "=f"(v.y), "=f"(v.z), "=f"(v.w) : "l"(p), "l"(pol));
    return v;
}

__global__ __launch_bounds__(256)
void build_kernel(const float* __restrict__ image,
                  const float* __restrict__ theta,
                  const float* __restrict__ weight)
{
    int idx = blockIdx.x * 256 + threadIdx.x;
    if (idx >= NPIX) return;
    int w = idx & (WW - 1);
    int h = (idx >> 9) & (HH - 1);
    int b = idx >> 18;

    float t0 = theta[0], t1 = theta[1], t2 = theta[2];
    const float* img = image + b * HW;
    float c = img[h * WW + w] * 255.0f;

    float A[9];
#pragma unroll
    for (int k = 0; k < 9; k++) {
        int dx = k / 3 - 1, dy = k % 3 - 1;
        int hh = h + dx, ww = w + dy;
        float e = 0.0f;
        if ((unsigned)hh < HH && (unsigned)ww < WW) {
            float d    = img[hh * WW + ww] * 255.0f - c;
            float dist = t0 * (float)(dx * dx) + t1 * (float)(dy * dy) + t2 * d * d;
            e = __expf(-0.5f * dist);
        }
        A[k] = __expf(e);          // invalid neighbor -> exp(0) = 1
    }

    // Sum S from the fp16-ROUNDED values: exactly what the message pass will
    // read (forward at p and backward at p-d are bit-identical by symmetry).
    float S = AC;
#pragma unroll
    for (int k = 0; k < 9; k++)
        if (k != 4) S += __half2float(__float2half(A[k]));

    float invSw = 0.5f * weight[0] / S;
    g_A[0][idx] = __float2half(A[5]);   // (0, 1)
    g_A[1][idx] = __float2half(A[6]);   // (1,-1)
    g_A[2][idx] = __float2half(A[7]);   // (1, 0)
    g_A[3][idx] = __float2half(A[8]);   // (1, 1)
    g_invS[idx] = __float2half(invSw);
}

__device__ __forceinline__ float2 h2f(const u32 u) {
    return __half22float2(*reinterpret_cast<const __half2*>(&u));
}

__global__ __launch_bounds__(256)
void message_pass(const float* __restrict__ pin,
                  const float* __restrict__ unary,
                  float* __restrict__ pout)
{
    int q = blockIdx.x * 256 + threadIdx.x;          // quad index
    if (q >= NPIX / 4) return;
    int w4 = (q & (WW / 4 - 1)) << 2;
    int h  = (q >> 7) & (HH - 1);
    int b  = q >> 16;
    int base    = b * HW;
    int rowbase = base + h * WW;
    u64 pol = mk_policy();

    // pred neighborhood: 3 rows x cols [w4-1 .. w4+4], zero-padded
    float row[3][6];
#pragma unroll
    for (int r = 0; r < 3; r++) {
        int hh = h + r - 1;
        if ((unsigned)hh >= HH) {
#pragma unroll
            for (int c = 0; c < 6; c++) row[r][c] = 0.0f;
        } else {
            const float* p = pin + base + hh * WW;
            float4 v = *(const float4*)(p + w4);
            row[r][1] = v.x; row[r][2] = v.y; row[r][3] = v.z; row[r][4] = v.w;
            row[r][0] = (w4 > 0)      ? p[w4 - 1] : 0.0f;
            row[r][5] = (w4 + 4 < WW) ? p[w4 + 4] : 0.0f;
        }
    }

    // center term
    float a0 = AC * row[1][1], a1 = AC * row[1][2];
    float a2 = AC * row[1][3], a3 = AC * row[1][4];

    const u32 ONES2 = 0x3C003C00u;  // half2(1,1)
    const __half* P0 = g_A[0], *P1 = g_A[1], *P2 = g_A[2], *P3 = g_A[3];
    int up = rowbase - WW + w4;          // row h-1 base index (valid iff h>0)
    int cw = rowbase + w4;

    // ---- dir0 (0,1): forward halves cover cols w4..w4+3 (also reused by B0)
    {
        uint2 rv = ldg_el_u2(&P0[cw], pol);
        float2 f01 = h2f(rv.x), f23 = h2f(rv.y);
        a0 += f01.x * row[1][2]; a1 += f01.y * row[1][3];
        a2 += f23.x * row[1][4]; a3 += f23.y * row[1][5];
        // backward (0,-1): plane0 at (h, w4-1..w4+2), OOB col -> 1
        u32 ta = (w4 > 0) ? ldg_el_u1(&P0[cw - 2], pol) : ONES2;
        float2 fa = h2f(ta);
        a0 += fa.y  * row[1][0]; a1 += f01.x * row[1][1];
        a2 += f01.y * row[1][2]; a3 += f23.x * row[1][3];
    }
    // ---- dir1 (1,-1): forward
    {
        uint2 rv = ldg_el_u2(&P1[cw], pol);
        float2 f01 = h2f(rv.x), f23 = h2f(rv.y);
        a0 += f01.x * row[2][0]; a1 += f01.y * row[2][1];
        a2 += f23.x * row[2][2]; a3 += f23.y * row[2][3];
        // backward (-1,1): plane1 at (h-1, w4+1..w4+4), OOB -> 1
        u32 tb = ONES2, tc = ONES2, td = ONES2;
        if (h > 0) {
            tb = ldg_el_u1(&P1[up], pol);
            tc = ldg_el_u1(&P1[up + 2], pol);
            if (w4 + 4 < WW) td = ldg_el_u1(&P1[up + 4], pol);
        }
        float2 fb = h2f(tb), fc = h2f(tc), fd = h2f(td);
        a0 += fb.y * row[0][2]; a1 += fc.x * row[0][3];
        a2 += fc.y * row[0][4]; a3 += fd.x * row[0][5];
    }
    // ---- dir2 (1,0): forward
    {
        uint2 rv = ldg_el_u2(&P2[cw], pol);
        float2 f01 = h2f(rv.x), f23 = h2f(rv.y);
        a0 += f01.x * row[2][1]; a1 += f01.y * row[2][2];
        a2 += f23.x * row[2][3]; a3 += f23.y * row[2][4];
        // backward (-1,0): plane2 at (h-1, w4..w4+3) aligned, OOB row -> 1
        uint2 bv; bv.x = ONES2; bv.y = ONES2;
        if (h > 0) bv = ldg_el_u2(&P2[up], pol);
        float2 b01 = h2f(bv.x), b23 = h2f(bv.y);
        a0 += b01.x * row[0][1]; a1 += b01.y * row[0][2];
        a2 += b23.x * row[0][3]; a3 += b23.y * row[0][4];
    }
    // ---- dir3 (1,1): forward
    {
        uint2 rv = ldg_el_u2(&P3[cw], pol);
        float2 f01 = h2f(rv.x), f23 = h2f(rv.y);
        a0 += f01.x * row[2][2]; a1 += f01.y * row[2][3];
        a2 += f23.x * row[2][4]; a3 += f23.y * row[2][5];
        // backward (-1,-1): plane3 at (h-1, w4-1..w4+2), OOB -> 1
        u32 ta = ONES2, tb = ONES2, tc = ONES2;
        if (h > 0) {
            if (w4 > 0) ta = ldg_el_u1(&P3[up - 2], pol);
            tb = ldg_el_u1(&P3[up], pol);
            tc = ldg_el_u1(&P3[up + 2], pol);
        }
        float2 fa = h2f(ta), fb = h2f(tb), fc = h2f(tc);
        a0 += fa.y * row[0][0]; a1 += fb.x * row[0][1];
        a2 += fb.y * row[0][2]; a3 += fc.x * row[0][3];
    }

    // normalize (0.5*weight folded in) + unary
    uint2 sv = ldg_el_u2(&g_invS[cw], pol);
    float2 s01 = h2f(sv.x), s23 = h2f(sv.y);
    float4 u = ldg_el_f4(unary + rowbase + w4, pol);
    float4 o;
    o.x = 0.5f * u.x + s01.x * a0;
    o.y = 0.5f * u.y + s01.y * a1;
    o.z = 0.5f * u.z + s23.x * a2;
    o.w = 0.5f * u.w + s23.y * a3;
    *(float4*)(pout + rowbase + w4) = o;
}

extern "C" void kernel_launch(void* const* d_in, const int* in_sizes, int n_in,
                              void* d_out, int out_size)
{
    const float* image  = (const float*)d_in[0];
    const float* unary  = (const float*)d_in[1];
    const float* theta  = (const float*)d_in[2];
    const float* weight = (const float*)d_in[3];
    float* out = (float*)d_out;

    void* baddr = nullptr;
    cudaGetSymbolAddress(&baddr, g_buf);   // non-stream API: capture-safe
    float* buf0 = (float*)baddr;
    float* buf1 = buf0 + NPIX;

    build_kernel<<<NPIX / 256, 256>>>(image, theta, weight);

    for (int i = 0; i < 10; i++) {
        const float* pin  = (i == 0) ? unary : (((i - 1) & 1) ? buf1 : buf0);
        float*       pout = (i == 9) ? out   : ((i & 1) ? buf1 : buf0);
        message_pass<<<(NPIX / 4) / 256, 256>>>(pin, unary, pout);
    }
}